// round 4
// baseline (speedup 1.0000x reference)
#include <cuda_runtime.h>
#include <math.h>

#define BB 8
#define SS 128
#define DD 256
#define HH 8
#define TT 129
#define HDIM 32

typedef unsigned long long ull;

// Scratch (no allocations allowed)
__device__ float g_A [BB*SS*DD];     // desc @ We1[:256] + be1
__device__ float g_Bm[BB*SS*DD];     // desc @ We1[256:]
__device__ float g_V [BB*TT*DD];     // nv @ Wv + bv
__device__ float g_u [DD*HH];        // We2 folded with wa_e
__device__ float g_wq[DD*HH];
__device__ float g_wk[DD*HH];
__device__ float g_qa[BB*HH*TT];     // includes bq_eff + ba + be2_eff
__device__ float g_ka[BB*HH*TT];     // includes bk_eff
__device__ float g_beff[3*HH];
__device__ float g_bias[BB*HH*SS*SS]; // log-odds prior bias
__device__ float g_sA[BB*SS];        // row sums of A'
__device__ float g_qA[BB*SS];        // row sumsq of A'
__device__ float g_sB[BB*SS];
__device__ float g_qB[BB*SS];
__device__ float g_G [BB*SS*SS];     // Gram: dot(A'_i, Bm_j)

// ---- f32x2 helpers -------------------------------------------------------
__device__ __forceinline__ ull pk(float a, float b) {
    ull r; asm("mov.b64 %0,{%1,%2};" : "=l"(r) : "f"(a), "f"(b)); return r;
}
__device__ __forceinline__ void upk(ull v, float& a, float& b) {
    asm("mov.b64 {%0,%1},%2;" : "=f"(a), "=f"(b) : "l"(v));
}
__device__ __forceinline__ ull add2(ull a, ull b) {
    ull r; asm("add.rn.f32x2 %0,%1,%2;" : "=l"(r) : "l"(a), "l"(b)); return r;
}
__device__ __forceinline__ ull mul2(ull a, ull b) {
    ull r; asm("mul.rn.f32x2 %0,%1,%2;" : "=l"(r) : "l"(a), "l"(b)); return r;
}
__device__ __forceinline__ ull fma2(ull a, ull b, ull c) {
    ull r; asm("fma.rn.f32x2 %0,%1,%2,%3;" : "=l"(r) : "l"(a), "l"(b), "l"(c)); return r;
}
__device__ __forceinline__ ull relu2(ull v) {
    ull a; asm("and.b64 %0,%1,0x7FFFFFFF7FFFFFFF;" : "=l"(a) : "l"(v));
    const ull HALF2 = 0x3F0000003F000000ULL;
    return mul2(add2(v, a), HALF2);
}

// ---------------------------------------------------------------------------
__global__ void k_setup(const float* __restrict__ Wq, const float* __restrict__ Wk,
                        const float* __restrict__ We2, const float* __restrict__ wa,
                        const float* __restrict__ bq, const float* __restrict__ bk,
                        const float* __restrict__ be2) {
    __shared__ float wa_s[96];
    int d = threadIdx.x;
    if (d < 96) wa_s[d] = wa[d];
    __syncthreads();
    #pragma unroll
    for (int h = 0; h < 8; h++) {
        float s1 = 0.f, s2 = 0.f, s3 = 0.f;
        #pragma unroll 8
        for (int e = 0; e < 32; e++) {
            int c = h * 32 + e;
            s1 += Wq [d * 256 + c] * wa_s[e];
            s2 += Wk [d * 256 + c] * wa_s[32 + e];
            s3 += We2[d * 256 + c] * wa_s[64 + e];
        }
        g_wq[d * 8 + h] = s1;
        g_wk[d * 8 + h] = s2;
        g_u [d * 8 + h] = s3;
    }
    if (d < 24) {
        int h = d & 7, which = d >> 3;
        const float* bp = (which == 0) ? bq : (which == 1) ? bk : be2;
        int wo = which * 32;
        float s = 0.f;
        for (int e = 0; e < 32; e++) s += bp[h * 32 + e] * wa_s[wo + e];
        g_beff[d] = s;
    }
}

// ---------------------------------------------------------------------------
__device__ __forceinline__ void gemm_tile(const float* __restrict__ X,
                                          const float* __restrict__ W,
                                          const float* __restrict__ bias,
                                          int M, int wRowOff, int bm, int bn,
                                          float* __restrict__ C,
                                          float* Xs, float* Ws) {
    int tid = threadIdx.x;
    int tr = (tid >> 4) << 2;
    int tc = (tid & 15) << 2;
    float acc[4][4];
    #pragma unroll
    for (int r = 0; r < 4; r++)
        #pragma unroll
        for (int c = 0; c < 4; c++) acc[r][c] = 0.f;

    for (int k0 = 0; k0 < 256; k0 += 32) {
        #pragma unroll
        for (int l = 0; l < 8; l++) {
            int idx = tid + l * 256;
            int r = idx >> 5, c = idx & 31;
            int gr = bm + r;
            Xs[r * 33 + c] = (gr < M) ? X[gr * 256 + k0 + c] : 0.f;
            int r2 = idx >> 6, c2 = idx & 63;
            Ws[r2 * 64 + c2] = W[(wRowOff + k0 + r2) * 256 + bn + c2];
        }
        __syncthreads();
        #pragma unroll
        for (int kk = 0; kk < 32; kk++) {
            float xv[4], wv[4];
            #pragma unroll
            for (int r = 0; r < 4; r++) xv[r] = Xs[(tr + r) * 33 + kk];
            #pragma unroll
            for (int c = 0; c < 4; c++) wv[c] = Ws[kk * 64 + tc + c];
            #pragma unroll
            for (int r = 0; r < 4; r++)
                #pragma unroll
                for (int c = 0; c < 4; c++) acc[r][c] = fmaf(xv[r], wv[c], acc[r][c]);
        }
        __syncthreads();
    }
    #pragma unroll
    for (int r = 0; r < 4; r++) {
        int gr = bm + tr + r;
        if (gr < M) {
            #pragma unroll
            for (int c = 0; c < 4; c++) {
                float v = acc[r][c];
                if (bias) v += bias[bn + tc + c];
                C[gr * 256 + bn + tc + c] = v;
            }
        }
    }
}

__global__ void __launch_bounds__(256) k_fused(const float* __restrict__ desc,
                                               const float* __restrict__ nv,
                                               const float* __restrict__ prior,
                                               const float* __restrict__ We1,
                                               const float* __restrict__ be1,
                                               const float* __restrict__ Wv,
                                               const float* __restrict__ bv,
                                               const float* __restrict__ ba) {
    __shared__ float Xs[64 * 33];
    __shared__ float Ws[32 * 64];
    int t = blockIdx.x;
    int tid = threadIdx.x;
    if (t < 128) {
        int mt = t & 15, nt = t >> 4;
        bool isB = nt >= 4;
        gemm_tile(desc, We1, isB ? (const float*)0 : be1, BB * SS,
                  isB ? 256 : 0, mt * 64, (nt & 3) * 64,
                  isB ? g_Bm : g_A, Xs, Ws);
    } else if (t < 196) {
        int t2 = t - 128;
        int mt = t2 % 17, nt = t2 / 17;
        gemm_tile(nv, Wv, bv, BB * TT, 0, mt * 64, nt * 64, g_V, Xs, Ws);
    } else if (t < 325) {
        int w = tid >> 5, lane = tid & 31;
        int row = (t - 196) * 8 + w;
        int b = row / TT, tt = row % TT;
        float accq[8], acck[8];
        #pragma unroll
        for (int h = 0; h < 8; h++) { accq[h] = 0.f; acck[h] = 0.f; }
        #pragma unroll
        for (int k = 0; k < 8; k++) {
            int d = lane + 32 * k;
            float xv = nv[row * DD + d];
            #pragma unroll
            for (int h = 0; h < 8; h++) {
                accq[h] = fmaf(xv, g_wq[d * 8 + h], accq[h]);
                acck[h] = fmaf(xv, g_wk[d * 8 + h], acck[h]);
            }
        }
        #pragma unroll
        for (int h = 0; h < 8; h++) {
            #pragma unroll
            for (int off = 16; off; off >>= 1) {
                accq[h] += __shfl_xor_sync(0xffffffffu, accq[h], off);
                acck[h] += __shfl_xor_sync(0xffffffffu, acck[h], off);
            }
        }
        if (lane == 0) {
            float bav = ba[0];
            #pragma unroll
            for (int h = 0; h < 8; h++) {
                g_qa[(b * HH + h) * TT + tt] = accq[h] + g_beff[h] + bav + g_beff[16 + h];
                g_ka[(b * HH + h) * TT + tt] = acck[h] + g_beff[8 + h];
            }
        }
    } else {
        const int N = BB * HH * SS * SS;
        int base = (t - 325) * 256 + tid;
        for (int idx = base; idx < N; idx += 128 * 256) {
            float p = prior[idx];
            p = fminf(fmaxf(p, 1e-6f), 1.f - 1e-6f);
            g_bias[idx] = __logf(p) - __logf(1.f - p);
        }
    }
}

// ---------------------------------------------------------------------------
// Gram G = A' @ Bm^T per batch (blocks 0..31) + row sums/sumsq (blocks 32..63)
__global__ void __launch_bounds__(256) k_stats() {
    __shared__ float As[64 * 33];
    __shared__ float Bs[32 * 65];
    int t = blockIdx.x, tid = threadIdx.x;
    if (t < 32) {
        int b = t >> 2, q = t & 3;
        int ti = (q >> 1) * 64, tj = (q & 1) * 64;
        int tr = (tid >> 4) << 2, tc = (tid & 15) << 2;
        float acc[4][4];
        #pragma unroll
        for (int r = 0; r < 4; r++)
            #pragma unroll
            for (int c = 0; c < 4; c++) acc[r][c] = 0.f;
        for (int k0 = 0; k0 < 256; k0 += 32) {
            #pragma unroll
            for (int l = 0; l < 8; l++) {
                int idx = tid + l * 256;
                int c = idx & 31, r = idx >> 5;
                As[r * 33 + c] = g_A[(b * 128 + ti + r) * 256 + k0 + c];
            }
            #pragma unroll
            for (int l = 0; l < 8; l++) {
                int idx = tid + l * 256;
                int c = idx & 31, r = idx >> 5;
                Bs[c * 65 + r] = g_Bm[(b * 128 + tj + r) * 256 + k0 + c];
            }
            __syncthreads();
            #pragma unroll
            for (int kk = 0; kk < 32; kk++) {
                float xv[4], wv[4];
                #pragma unroll
                for (int r = 0; r < 4; r++) xv[r] = As[(tr + r) * 33 + kk];
                #pragma unroll
                for (int c = 0; c < 4; c++) wv[c] = Bs[kk * 65 + tc + c];
                #pragma unroll
                for (int r = 0; r < 4; r++)
                    #pragma unroll
                    for (int c = 0; c < 4; c++) acc[r][c] = fmaf(xv[r], wv[c], acc[r][c]);
            }
            __syncthreads();
        }
        #pragma unroll
        for (int r = 0; r < 4; r++)
            #pragma unroll
            for (int c = 0; c < 4; c++)
                g_G[(b * 128 + ti + tr + r) * 128 + tj + tc + c] = acc[r][c];
    } else {
        int w = tid >> 5, lane = tid & 31;
        int r0 = (t - 32) * 64;
        for (int it = 0; it < 8; it++) {
            int row = r0 + w * 8 + it;
            const float* src = (row < 1024) ? (g_A + row * 256) : (g_Bm + (row - 1024) * 256);
            const float4* sp = (const float4*)(src + lane * 8);
            float4 v0 = sp[0], v1 = sp[1];
            float s = v0.x + v0.y + v0.z + v0.w + v1.x + v1.y + v1.z + v1.w;
            float q = v0.x*v0.x + v0.y*v0.y + v0.z*v0.z + v0.w*v0.w
                    + v1.x*v1.x + v1.y*v1.y + v1.z*v1.z + v1.w*v1.w;
            #pragma unroll
            for (int off = 16; off; off >>= 1) {
                s += __shfl_xor_sync(0xffffffffu, s, off);
                q += __shfl_xor_sync(0xffffffffu, q, off);
            }
            if (lane == 0) {
                if (row < 1024) { g_sA[row] = s; g_qA[row] = q; }
                else            { g_sB[row - 1024] = s; g_qB[row - 1024] = q; }
            }
        }
    }
}

// ---------------------------------------------------------------------------
// k_edge: block = (b, i-tile of 4). 8 warps x 16 j each. lane holds 8 consecutive d.
__global__ void __launch_bounds__(256) k_edge(const float* __restrict__ lng,
                                              const float* __restrict__ lnb,
                                              float* __restrict__ out_attn) {
    int blk = blockIdx.x;
    int b = blk / 33, it = blk % 33;
    int base = it * 4;
    int tid = threadIdx.x, w = tid >> 5, lane = tid & 31;

    __shared__ __align__(16) float a_sh[4 * 256];
    __shared__ float e_sh[4][HH][132];
    __shared__ float sA_sh[128], qA_sh[128], sB_sh[128], qB_sh[128];

    if (tid < 128) {
        sA_sh[tid] = g_sA[b * 128 + tid];
        qA_sh[tid] = g_qA[b * 128 + tid];
    } else {
        int t2 = tid - 128;
        sB_sh[t2] = g_sB[b * 128 + t2];
        qB_sh[t2] = g_qB[b * 128 + t2];
    }
    #pragma unroll
    for (int rep = 0; rep < 4; rep++) {
        int fidx = rep * 256 + tid;
        int s = fidx >> 8, d = fidx & 255;
        int row = base - 1 + s;
        if (row >= 0 && row < 128)
            a_sh[s * 256 + d] = g_A[(b * 128 + row) * 256 + d];
    }

    int d0 = lane * 8;
    ull u2[4][8], g2[4], bt2[4];
    #pragma unroll
    for (int k2 = 0; k2 < 4; k2++) {
        const float4* ua = (const float4*)(g_u + (d0 + 2 * k2) * 8);
        const float4* ub = (const float4*)(g_u + (d0 + 2 * k2 + 1) * 8);
        float4 A0 = ua[0], A1 = ua[1], B0 = ub[0], B1 = ub[1];
        u2[k2][0] = pk(A0.x, B0.x); u2[k2][1] = pk(A0.y, B0.y);
        u2[k2][2] = pk(A0.z, B0.z); u2[k2][3] = pk(A0.w, B0.w);
        u2[k2][4] = pk(A1.x, B1.x); u2[k2][5] = pk(A1.y, B1.y);
        u2[k2][6] = pk(A1.z, B1.z); u2[k2][7] = pk(A1.w, B1.w);
        g2[k2]  = pk(lng[d0 + 2 * k2], lng[d0 + 2 * k2 + 1]);
        bt2[k2] = pk(lnb[d0 + 2 * k2], lnb[d0 + 2 * k2 + 1]);
    }
    __syncthreads();

    const float invD = 1.f / 256.f;
    int jbase = w * 16 + 1;
    #pragma unroll 1
    for (int jo = 0; jo < 16; jo++) {
        int j = jbase + jo;                // 1..128
        const float4* bmp = (const float4*)(g_Bm + (b * 128 + j - 1) * 256 + d0);
        float4 b0 = bmp[0], b1 = bmp[1];
        ull bm2[4] = { pk(b0.x, b0.y), pk(b0.z, b0.w), pk(b1.x, b1.y), pk(b1.z, b1.w) };
        float sBj = sB_sh[j - 1], qBj = qB_sh[j - 1];

        #pragma unroll
        for (int s = 0; s < 4; s++) {
            int i = base + s;
            if (i > 128) break;
            float sAx, qAx, Gx;
            ull a2[4];
            if (i == 0) {
                sAx = sA_sh[j - 1]; qAx = qA_sh[j - 1];
                Gx = g_G[(b * 128 + j - 1) * 128 + (j - 1)];
                const float4* ap = (const float4*)(g_A + (b * 128 + j - 1) * 256 + d0);
                float4 a0 = ap[0], a1 = ap[1];
                a2[0] = pk(a0.x, a0.y); a2[1] = pk(a0.z, a0.w);
                a2[2] = pk(a1.x, a1.y); a2[3] = pk(a1.z, a1.w);
            } else {
                sAx = sA_sh[i - 1]; qAx = qA_sh[i - 1];
                Gx = g_G[(b * 128 + i - 1) * 128 + (j - 1)];
                const float4* ap = (const float4*)(a_sh + s * 256 + d0);
                float4 a0 = ap[0], a1 = ap[1];
                a2[0] = pk(a0.x, a0.y); a2[1] = pk(a0.z, a0.w);
                a2[2] = pk(a1.x, a1.y); a2[3] = pk(a1.z, a1.w);
            }
            float ss = sAx + sBj;
            float s2v = qAx + qBj + 2.f * Gx;
            float mu = ss * invD;
            float var = fmaxf(s2v * invD - mu * mu, 0.f);
            float rs = rsqrtf(var + 1e-5f);
            float c0 = -mu * rs;
            ull rs2 = pk(rs, rs), c02 = pk(c0, c0);

            ull acc2[8];
            #pragma unroll
            for (int h = 0; h < 8; h++) acc2[h] = 0ULL;
            #pragma unroll
            for (int k2 = 0; k2 < 4; k2++) {
                ull x2 = add2(a2[k2], bm2[k2]);
                ull t2 = fma2(x2, rs2, c02);
                ull y2 = relu2(fma2(t2, g2[k2], bt2[k2]));
                #pragma unroll
                for (int h = 0; h < 8; h++) acc2[h] = fma2(y2, u2[k2][h], acc2[h]);
            }
            float acc[8];
            #pragma unroll
            for (int h = 0; h < 8; h++) {
                float lo, hi; upk(acc2[h], lo, hi);
                acc[h] = lo + hi;
            }
            bool b4 = (lane & 16), b3 = (lane & 8), b2 = (lane & 4);
            float v0, v1, v2, v3;
            {
                float t0 = b4 ? acc[0] : acc[4];
                float t1 = b4 ? acc[1] : acc[5];
                float t2_ = b4 ? acc[2] : acc[6];
                float t3 = b4 ? acc[3] : acc[7];
                v0 = (b4 ? acc[4] : acc[0]) + __shfl_xor_sync(0xffffffffu, t0, 16);
                v1 = (b4 ? acc[5] : acc[1]) + __shfl_xor_sync(0xffffffffu, t1, 16);
                v2 = (b4 ? acc[6] : acc[2]) + __shfl_xor_sync(0xffffffffu, t2_, 16);
                v3 = (b4 ? acc[7] : acc[3]) + __shfl_xor_sync(0xffffffffu, t3, 16);
            }
            float w0, w1;
            {
                float t0 = b3 ? v0 : v2;
                float t1 = b3 ? v1 : v3;
                w0 = (b3 ? v2 : v0) + __shfl_xor_sync(0xffffffffu, t0, 8);
                w1 = (b3 ? v3 : v1) + __shfl_xor_sync(0xffffffffu, t1, 8);
            }
            float r;
            {
                float tsel = b2 ? w0 : w1;
                r = (b2 ? w1 : w0) + __shfl_xor_sync(0xffffffffu, tsel, 4);
            }
            r += __shfl_xor_sync(0xffffffffu, r, 2);
            r += __shfl_xor_sync(0xffffffffu, r, 1);
            if ((lane & 3) == 0) e_sh[s][lane >> 2][j] = r;
        }
    }
    __syncthreads();

    // softmax: warp w = head w; loop i slots
    int h = w;
    #pragma unroll 1
    for (int s = 0; s < 4; s++) {
        int i = base + s;
        if (i > 128) break;
        float qv = g_qa[(b * HH + h) * TT + i];
        const float* kap = g_ka + (b * HH + h) * TT;
        const float* bi = g_bias + (((size_t)(b * HH + h) * SS) + (i - 1)) * SS;
        float lg[5];
        float mx = -3.4e38f;
        #pragma unroll
        for (int m = 0; m < 5; m++) {
            int j = lane + 32 * m;
            float L = -3.4e38f;
            if (j <= 128) {
                bool ok = (j >= 1) && (i == 0 || j != i);
                if (!ok) L = -1e9f;
                else {
                    L = e_sh[s][h][j] + qv + kap[j];
                    if (i >= 1) L += bi[j - 1];
                }
            }
            lg[m] = L;
            mx = fmaxf(mx, L);
        }
        #pragma unroll
        for (int off = 16; off; off >>= 1)
            mx = fmaxf(mx, __shfl_xor_sync(0xffffffffu, mx, off));
        float sum = 0.f;
        #pragma unroll
        for (int m = 0; m < 5; m++) {
            int j = lane + 32 * m;
            if (j <= 128) { lg[m] = __expf(lg[m] - mx); sum += lg[m]; }
            else lg[m] = 0.f;
        }
        #pragma unroll
        for (int off = 16; off; off >>= 1)
            sum += __shfl_xor_sync(0xffffffffu, sum, off);
        float inv = 1.f / sum;
        float* ao = out_attn + ((size_t)(b * HH + h) * TT + i) * TT;
        #pragma unroll
        for (int m = 0; m < 5; m++) {
            int j = lane + 32 * m;
            if (j <= 128) ao[j] = lg[m] * inv;
        }
    }
}

// ---------------------------------------------------------------------------
// ctx: block per (b,h,iq). Shared-staged attn rows (scalar coalesced loads).
__global__ void __launch_bounds__(256) k_ctx(const float* __restrict__ attn,
                                             float* __restrict__ out_basis) {
    int t = blockIdx.x;
    int b = t >> 5, h = (t >> 2) & 7, iq = t & 3;
    int i0q = iq * 32;
    int iend = (iq == 3) ? 129 : (i0q + 32);
    int tid = threadIdx.x, w = tid >> 5, lane = tid & 31;

    __shared__ __align__(16) float vsh[TT * 33];
    __shared__ __align__(16) float a_sh[8 * 132];

    for (int idx = tid; idx < TT * 32; idx += 256) {
        int j = idx >> 5, d = idx & 31;
        vsh[j * 33 + d] = g_V[((size_t)b * TT + j) * DD + h * HDIM + d];
    }
    __syncthreads();

    for (int i0 = i0q; i0 < iend; i0 += 8) {
        int rows = iend - i0; if (rows > 8) rows = 8;
        if (w < rows) {
            int i = i0 + w;
            const float* ar = attn + ((size_t)(b * HH + h) * TT + i) * TT;
            // scalar coalesced loads (attn row stride 129 floats is not 16B-aligned)
            #pragma unroll
            for (int m = 0; m < 4; m++)
                a_sh[w * 132 + lane + 32 * m] = ar[lane + 32 * m];
            if (lane == 0) a_sh[w * 132 + 128] = ar[128];
        }
        __syncthreads();
        if (w < rows) {
            int i = i0 + w;
            const float4* arow = (const float4*)(a_sh + w * 132);
            float acc = 0.f;
            #pragma unroll 8
            for (int jj = 0; jj < 32; jj++) {
                float4 av = arow[jj];
                int jb = jj * 4;
                acc = fmaf(av.x, vsh[(jb + 0) * 33 + lane], acc);
                acc = fmaf(av.y, vsh[(jb + 1) * 33 + lane], acc);
                acc = fmaf(av.z, vsh[(jb + 2) * 33 + lane], acc);
                acc = fmaf(av.w, vsh[(jb + 3) * 33 + lane], acc);
            }
            acc = fmaf(a_sh[w * 132 + 128], vsh[128 * 33 + lane], acc);
            out_basis[(((size_t)b * TT + i) * HH + h) * HDIM + lane] = acc;
        }
        __syncthreads();
    }
}

// ---------------------------------------------------------------------------
extern "C" void kernel_launch(void* const* d_in, const int* in_sizes, int n_in,
                              void* d_out, int out_size) {
    const float* desc  = (const float*)d_in[0];
    const float* nv    = (const float*)d_in[1];
    const float* prior = (const float*)d_in[2];
    const float* Wq    = (const float*)d_in[3];
    const float* bq    = (const float*)d_in[4];
    const float* Wk    = (const float*)d_in[5];
    const float* bk    = (const float*)d_in[6];
    const float* Wv    = (const float*)d_in[7];
    const float* bv    = (const float*)d_in[8];
    const float* wa    = (const float*)d_in[9];
    const float* ba    = (const float*)d_in[10];
    const float* We1   = (const float*)d_in[11];
    const float* be1   = (const float*)d_in[12];
    const float* lng   = (const float*)d_in[13];
    const float* lnb   = (const float*)d_in[14];
    const float* We2   = (const float*)d_in[15];
    const float* be2   = (const float*)d_in[16];

    float* out      = (float*)d_out;
    float* out_attn = out + (size_t)BB * TT * HH * HDIM;

    k_setup<<<1, 256>>>(Wq, Wk, We2, wa, bq, bk, be2);
    k_fused<<<453, 256>>>(desc, nv, prior, We1, be1, Wv, bv, ba);
    k_stats<<<64, 256>>>();
    k_edge<<<BB * 33, 256>>>(lng, lnb, out_attn);
    k_ctx<<<BB * HH * 4, 256>>>(out_attn, out);
}

// round 7
// speedup vs baseline: 1.9545x; 1.9545x over previous
#include <cuda_runtime.h>
#include <math.h>

#define BB 8
#define SS 128
#define DD 256
#define HH 8
#define TT 129
#define HDIM 32

typedef unsigned long long ull;

// Scratch (no allocations allowed)
__device__ float g_A [BB*SS*DD];     // desc @ We1[:256] + be1
__device__ float g_Bm[BB*SS*DD];     // desc @ We1[256:]
__device__ float g_V [BB*TT*DD];     // nv @ Wv + bv
__device__ float g_u [DD*HH];        // We2 folded with wa_e
__device__ float g_wq[DD*HH];
__device__ float g_wk[DD*HH];
__device__ float g_qa[BB*HH*TT];     // includes bq_eff + ba + be2_eff
__device__ float g_ka[BB*HH*TT];     // includes bk_eff
__device__ float g_beff[3*HH];
__device__ float g_bias[BB*HH*SS*SS]; // log-odds prior bias
__device__ float g_sA[BB*SS];
__device__ float g_qA[BB*SS];
__device__ float g_sB[BB*SS];
__device__ float g_qB[BB*SS];
__device__ float g_G [BB*SS*SS];     // Gram: dot(A'_i, Bm_j)

// ---- f32x2 helpers -------------------------------------------------------
__device__ __forceinline__ ull pk(float a, float b) {
    ull r; asm("mov.b64 %0,{%1,%2};" : "=l"(r) : "f"(a), "f"(b)); return r;
}
__device__ __forceinline__ void upk(ull v, float& a, float& b) {
    asm("mov.b64 {%0,%1},%2;" : "=f"(a), "=f"(b) : "l"(v));
}
__device__ __forceinline__ ull add2(ull a, ull b) {
    ull r; asm("add.rn.f32x2 %0,%1,%2;" : "=l"(r) : "l"(a), "l"(b)); return r;
}
__device__ __forceinline__ ull mul2(ull a, ull b) {
    ull r; asm("mul.rn.f32x2 %0,%1,%2;" : "=l"(r) : "l"(a), "l"(b)); return r;
}
__device__ __forceinline__ ull fma2(ull a, ull b, ull c) {
    ull r; asm("fma.rn.f32x2 %0,%1,%2,%3;" : "=l"(r) : "l"(a), "l"(b), "l"(c)); return r;
}
__device__ __forceinline__ ull relu2(ull v) {
    ull a; asm("and.b64 %0,%1,0x7FFFFFFF7FFFFFFF;" : "=l"(a) : "l"(v));
    const ull HALF2 = 0x3F0000003F000000ULL;
    return mul2(add2(v, a), HALF2);
}

// ---------------------------------------------------------------------------
// k_setup parallelized: blocks 0..23 = (which, h) projections; block 24 = biases
__global__ void __launch_bounds__(256) k_setup(
        const float* __restrict__ Wq, const float* __restrict__ Wk,
        const float* __restrict__ We2, const float* __restrict__ wa,
        const float* __restrict__ bq, const float* __restrict__ bk,
        const float* __restrict__ be2) {
    int blk = blockIdx.x;
    if (blk < 24) {
        int which = blk >> 3, h = blk & 7;
        const float* W = (which == 0) ? Wq : (which == 1) ? Wk : We2;
        float* dst = (which == 0) ? g_wq : (which == 1) ? g_wk : g_u;
        __shared__ float was[32];
        if (threadIdx.x < 32) was[threadIdx.x] = wa[which * 32 + threadIdx.x];
        __syncthreads();
        int d = threadIdx.x;
        const float4* wp = (const float4*)(W + d * 256 + h * 32);
        float s = 0.f;
        #pragma unroll
        for (int e4 = 0; e4 < 8; e4++) {
            float4 v = wp[e4];
            s = fmaf(v.x, was[e4*4+0], s);
            s = fmaf(v.y, was[e4*4+1], s);
            s = fmaf(v.z, was[e4*4+2], s);
            s = fmaf(v.w, was[e4*4+3], s);
        }
        dst[d * 8 + h] = s;
    } else {
        __shared__ float was[96];
        if (threadIdx.x < 96) was[threadIdx.x] = wa[threadIdx.x];
        __syncthreads();
        int d = threadIdx.x;
        if (d < 24) {
            int h = d & 7, which = d >> 3;
            const float* bp = (which == 0) ? bq : (which == 1) ? bk : be2;
            int wo = which * 32;
            float s = 0.f;
            for (int e = 0; e < 32; e++) s += bp[h * 32 + e] * was[wo + e];
            g_beff[d] = s;
        }
    }
}

// ---------------------------------------------------------------------------
// GEMM core: 64x64 tile, 256 thr, 4x4/thread, K-panel 16, reg-prefetch,
// both operands read as float4 from smem. XsT/Ws each [16][68].
__device__ __forceinline__ void gemm_tile64(const float* __restrict__ X,
                                            const float* __restrict__ W,
                                            const float* __restrict__ bias,
                                            int M, int wRowOff, int bm, int bn,
                                            float* __restrict__ C,
                                            float* XsT, float* Ws) {
    int tid = threadIdx.x;
    int xr = tid >> 2, xc = (tid & 3) * 4;     // X panel: row, k-col
    int wk = tid >> 4, wn = (tid & 15) * 4;    // W panel: k-row, n-col
    int tr = (tid >> 4) * 4, tc = (tid & 15) * 4;
    float acc[4][4];
    #pragma unroll
    for (int r = 0; r < 4; r++)
        #pragma unroll
        for (int c = 0; c < 4; c++) acc[r][c] = 0.f;

    int gr = bm + xr;
    float4 xv, wv;
    if (gr < M) xv = *(const float4*)&X[gr * 256 + xc];
    else xv = make_float4(0.f, 0.f, 0.f, 0.f);
    wv = *(const float4*)&W[(wRowOff + wk) * 256 + bn + wn];

    #pragma unroll 1
    for (int p = 0; p < 16; p++) {
        XsT[(xc + 0) * 68 + xr] = xv.x;
        XsT[(xc + 1) * 68 + xr] = xv.y;
        XsT[(xc + 2) * 68 + xr] = xv.z;
        XsT[(xc + 3) * 68 + xr] = xv.w;
        *(float4*)&Ws[wk * 68 + wn] = wv;
        __syncthreads();
        if (p < 15) {
            int k0 = (p + 1) * 16;
            if (gr < M) xv = *(const float4*)&X[gr * 256 + k0 + xc];
            wv = *(const float4*)&W[(wRowOff + k0 + wk) * 256 + bn + wn];
        }
        #pragma unroll
        for (int kk = 0; kk < 16; kk++) {
            float4 a = *(const float4*)&XsT[kk * 68 + tr];
            float4 b = *(const float4*)&Ws[kk * 68 + tc];
            acc[0][0] = fmaf(a.x, b.x, acc[0][0]); acc[0][1] = fmaf(a.x, b.y, acc[0][1]);
            acc[0][2] = fmaf(a.x, b.z, acc[0][2]); acc[0][3] = fmaf(a.x, b.w, acc[0][3]);
            acc[1][0] = fmaf(a.y, b.x, acc[1][0]); acc[1][1] = fmaf(a.y, b.y, acc[1][1]);
            acc[1][2] = fmaf(a.y, b.z, acc[1][2]); acc[1][3] = fmaf(a.y, b.w, acc[1][3]);
            acc[2][0] = fmaf(a.z, b.x, acc[2][0]); acc[2][1] = fmaf(a.z, b.y, acc[2][1]);
            acc[2][2] = fmaf(a.z, b.z, acc[2][2]); acc[2][3] = fmaf(a.z, b.w, acc[2][3]);
            acc[3][0] = fmaf(a.w, b.x, acc[3][0]); acc[3][1] = fmaf(a.w, b.y, acc[3][1]);
            acc[3][2] = fmaf(a.w, b.z, acc[3][2]); acc[3][3] = fmaf(a.w, b.w, acc[3][3]);
        }
        __syncthreads();
    }
    #pragma unroll
    for (int r = 0; r < 4; r++) {
        int gr2 = bm + tr + r;
        if (gr2 < M) {
            float4 v = make_float4(acc[r][0], acc[r][1], acc[r][2], acc[r][3]);
            if (bias) {
                v.x += bias[bn + tc + 0]; v.y += bias[bn + tc + 1];
                v.z += bias[bn + tc + 2]; v.w += bias[bn + tc + 3];
            }
            *(float4*)&C[gr2 * 256 + bn + tc] = v;
        }
    }
}

__global__ void __launch_bounds__(256) k_fused(const float* __restrict__ desc,
                                               const float* __restrict__ nv,
                                               const float* __restrict__ prior,
                                               const float* __restrict__ We1,
                                               const float* __restrict__ be1,
                                               const float* __restrict__ Wv,
                                               const float* __restrict__ bv,
                                               const float* __restrict__ ba) {
    __shared__ __align__(16) float XsT[16 * 68];
    __shared__ __align__(16) float Ws[16 * 68];
    int t = blockIdx.x;
    int tid = threadIdx.x;
    if (t < 128) {
        int mt = t & 15, nt = t >> 4;
        bool isB = nt >= 4;
        gemm_tile64(desc, We1, isB ? (const float*)0 : be1, BB * SS,
                    isB ? 256 : 0, mt * 64, (nt & 3) * 64,
                    isB ? g_Bm : g_A, XsT, Ws);
    } else if (t < 196) {
        int t2 = t - 128;
        int mt = t2 % 17, nt = t2 / 17;
        gemm_tile64(nv, Wv, bv, BB * TT, 0, mt * 64, nt * 64, g_V, XsT, Ws);
    } else if (t < 325) {
        int w = tid >> 5, lane = tid & 31;
        int row = (t - 196) * 8 + w;
        int b = row / TT, tt = row % TT;
        float accq[8], acck[8];
        #pragma unroll
        for (int h = 0; h < 8; h++) { accq[h] = 0.f; acck[h] = 0.f; }
        #pragma unroll
        for (int k = 0; k < 8; k++) {
            int d = lane + 32 * k;
            float xv = nv[row * DD + d];
            #pragma unroll
            for (int h = 0; h < 8; h++) {
                accq[h] = fmaf(xv, g_wq[d * 8 + h], accq[h]);
                acck[h] = fmaf(xv, g_wk[d * 8 + h], acck[h]);
            }
        }
        #pragma unroll
        for (int h = 0; h < 8; h++) {
            #pragma unroll
            for (int off = 16; off; off >>= 1) {
                accq[h] += __shfl_xor_sync(0xffffffffu, accq[h], off);
                acck[h] += __shfl_xor_sync(0xffffffffu, acck[h], off);
            }
        }
        if (lane == 0) {
            float bav = ba[0];
            #pragma unroll
            for (int h = 0; h < 8; h++) {
                g_qa[(b * HH + h) * TT + tt] = accq[h] + g_beff[h] + bav + g_beff[16 + h];
                g_ka[(b * HH + h) * TT + tt] = acck[h] + g_beff[8 + h];
            }
        }
    } else {
        const int N = BB * HH * SS * SS;
        int base = (t - 325) * 256 + tid;
        for (int idx = base; idx < N; idx += 128 * 256) {
            float p = prior[idx];
            p = fminf(fmaxf(p, 1e-6f), 1.f - 1e-6f);
            g_bias[idx] = __logf(p) - __logf(1.f - p);
        }
    }
}

// ---------------------------------------------------------------------------
// k_stats: blocks 0..31 Gram (both operands transposed-on-store), 32..63 row stats
__global__ void __launch_bounds__(256) k_stats() {
    __shared__ __align__(16) float As[16 * 68];
    __shared__ __align__(16) float Bs[16 * 68];
    int t = blockIdx.x, tid = threadIdx.x;
    if (t < 32) {
        int b = t >> 2, q = t & 3;
        int ti = (q >> 1) * 64, tj = (q & 1) * 64;
        int xr = tid >> 2, xc = (tid & 3) * 4;
        int tr = (tid >> 4) * 4, tc = (tid & 15) * 4;
        float acc[4][4];
        #pragma unroll
        for (int r = 0; r < 4; r++)
            #pragma unroll
            for (int c = 0; c < 4; c++) acc[r][c] = 0.f;

        const float* Abase = g_A + (b * 128 + ti) * 256;
        const float* Bbase = g_Bm + (b * 128 + tj) * 256;
        float4 av = *(const float4*)&Abase[xr * 256 + xc];
        float4 bv = *(const float4*)&Bbase[xr * 256 + xc];
        #pragma unroll 1
        for (int p = 0; p < 16; p++) {
            As[(xc + 0) * 68 + xr] = av.x; As[(xc + 1) * 68 + xr] = av.y;
            As[(xc + 2) * 68 + xr] = av.z; As[(xc + 3) * 68 + xr] = av.w;
            Bs[(xc + 0) * 68 + xr] = bv.x; Bs[(xc + 1) * 68 + xr] = bv.y;
            Bs[(xc + 2) * 68 + xr] = bv.z; Bs[(xc + 3) * 68 + xr] = bv.w;
            __syncthreads();
            if (p < 15) {
                int k0 = (p + 1) * 16;
                av = *(const float4*)&Abase[xr * 256 + k0 + xc];
                bv = *(const float4*)&Bbase[xr * 256 + k0 + xc];
            }
            #pragma unroll
            for (int kk = 0; kk < 16; kk++) {
                float4 a = *(const float4*)&As[kk * 68 + tr];
                float4 b2 = *(const float4*)&Bs[kk * 68 + tc];
                acc[0][0] = fmaf(a.x, b2.x, acc[0][0]); acc[0][1] = fmaf(a.x, b2.y, acc[0][1]);
                acc[0][2] = fmaf(a.x, b2.z, acc[0][2]); acc[0][3] = fmaf(a.x, b2.w, acc[0][3]);
                acc[1][0] = fmaf(a.y, b2.x, acc[1][0]); acc[1][1] = fmaf(a.y, b2.y, acc[1][1]);
                acc[1][2] = fmaf(a.y, b2.z, acc[1][2]); acc[1][3] = fmaf(a.y, b2.w, acc[1][3]);
                acc[2][0] = fmaf(a.z, b2.x, acc[2][0]); acc[2][1] = fmaf(a.z, b2.y, acc[2][1]);
                acc[2][2] = fmaf(a.z, b2.z, acc[2][2]); acc[2][3] = fmaf(a.z, b2.w, acc[2][3]);
                acc[3][0] = fmaf(a.w, b2.x, acc[3][0]); acc[3][1] = fmaf(a.w, b2.y, acc[3][1]);
                acc[3][2] = fmaf(a.w, b2.z, acc[3][2]); acc[3][3] = fmaf(a.w, b2.w, acc[3][3]);
            }
            __syncthreads();
        }
        #pragma unroll
        for (int r = 0; r < 4; r++) {
            float4 v = make_float4(acc[r][0], acc[r][1], acc[r][2], acc[r][3]);
            *(float4*)&g_G[(b * 128 + ti + tr + r) * 128 + tj + tc] = v;
        }
    } else {
        int w = tid >> 5, lane = tid & 31;
        int r0 = (t - 32) * 64;
        for (int it = 0; it < 8; it++) {
            int row = r0 + w * 8 + it;
            const float* src = (row < 1024) ? (g_A + row * 256) : (g_Bm + (row - 1024) * 256);
            const float4* sp = (const float4*)(src + lane * 8);
            float4 v0 = sp[0], v1 = sp[1];
            float s = v0.x + v0.y + v0.z + v0.w + v1.x + v1.y + v1.z + v1.w;
            float q = v0.x*v0.x + v0.y*v0.y + v0.z*v0.z + v0.w*v0.w
                    + v1.x*v1.x + v1.y*v1.y + v1.z*v1.z + v1.w*v1.w;
            #pragma unroll
            for (int off = 16; off; off >>= 1) {
                s += __shfl_xor_sync(0xffffffffu, s, off);
                q += __shfl_xor_sync(0xffffffffu, q, off);
            }
            if (lane == 0) {
                if (row < 1024) { g_sA[row] = s; g_qA[row] = q; }
                else            { g_sB[row - 1024] = s; g_qB[row - 1024] = q; }
            }
        }
    }
}

// ---------------------------------------------------------------------------
// k_edge: block = (b, i-tile of 4). u in shared (frees ~64 regs -> higher occ).
__global__ void __launch_bounds__(256) k_edge(const float* __restrict__ lng,
                                              const float* __restrict__ lnb,
                                              float* __restrict__ out_attn) {
    int blk = blockIdx.x;
    int b = blk / 33, it = blk % 33;
    int base = it * 4;
    int tid = threadIdx.x, w = tid >> 5, lane = tid & 31;

    __shared__ __align__(16) float a_sh[4 * 256];
    __shared__ float e_sh[4][HH][132];
    __shared__ float sA_sh[128], qA_sh[128], sB_sh[128], qB_sh[128];
    __shared__ ull ush[4 * 8 * 32];     // [k2][h][lane]

    if (tid < 128) {
        sA_sh[tid] = g_sA[b * 128 + tid];
        qA_sh[tid] = g_qA[b * 128 + tid];
    } else {
        int t2 = tid - 128;
        sB_sh[t2] = g_sB[b * 128 + t2];
        qB_sh[t2] = g_qB[b * 128 + t2];
    }
    // fill ush: thread (q=tid>>5 handles h=q for its lane)
    {
        int q = tid >> 5;
        #pragma unroll
        for (int k2 = 0; k2 < 4; k2++) {
            int dl = lane * 8 + 2 * k2;
            ush[(k2 * 8 + q) * 32 + lane] = pk(g_u[dl * 8 + q], g_u[(dl + 1) * 8 + q]);
        }
    }
    #pragma unroll
    for (int rep = 0; rep < 4; rep++) {
        int fidx = rep * 256 + tid;
        int s = fidx >> 8, d = fidx & 255;
        int row = base - 1 + s;
        if (row >= 0 && row < 128)
            a_sh[s * 256 + d] = g_A[(b * 128 + row) * 256 + d];
    }

    int d0 = lane * 8;
    ull g2[4], bt2[4];
    #pragma unroll
    for (int k2 = 0; k2 < 4; k2++) {
        g2[k2]  = pk(lng[d0 + 2 * k2], lng[d0 + 2 * k2 + 1]);
        bt2[k2] = pk(lnb[d0 + 2 * k2], lnb[d0 + 2 * k2 + 1]);
    }
    __syncthreads();

    const float invD = 1.f / 256.f;
    int jbase = w * 16 + 1;
    #pragma unroll 1
    for (int jo = 0; jo < 16; jo++) {
        int j = jbase + jo;                // 1..128
        const float4* bmp = (const float4*)(g_Bm + (b * 128 + j - 1) * 256 + d0);
        float4 b0 = bmp[0], b1 = bmp[1];
        ull bm2[4] = { pk(b0.x, b0.y), pk(b0.z, b0.w), pk(b1.x, b1.y), pk(b1.z, b1.w) };
        float sBj = sB_sh[j - 1], qBj = qB_sh[j - 1];

        #pragma unroll
        for (int s = 0; s < 4; s++) {
            int i = base + s;
            if (i > 128) break;
            float sAx, qAx, Gx;
            ull a2[4];
            if (i == 0) {
                sAx = sA_sh[j - 1]; qAx = qA_sh[j - 1];
                Gx = g_G[(b * 128 + j - 1) * 128 + (j - 1)];
                const float4* ap = (const float4*)(g_A + (b * 128 + j - 1) * 256 + d0);
                float4 a0 = ap[0], a1 = ap[1];
                a2[0] = pk(a0.x, a0.y); a2[1] = pk(a0.z, a0.w);
                a2[2] = pk(a1.x, a1.y); a2[3] = pk(a1.z, a1.w);
            } else {
                sAx = sA_sh[i - 1]; qAx = qA_sh[i - 1];
                Gx = g_G[(b * 128 + i - 1) * 128 + (j - 1)];
                const float4* ap = (const float4*)(a_sh + s * 256 + d0);
                float4 a0 = ap[0], a1 = ap[1];
                a2[0] = pk(a0.x, a0.y); a2[1] = pk(a0.z, a0.w);
                a2[2] = pk(a1.x, a1.y); a2[3] = pk(a1.z, a1.w);
            }
            float ss = sAx + sBj;
            float s2v = qAx + qBj + 2.f * Gx;
            float mu = ss * invD;
            float var = fmaxf(s2v * invD - mu * mu, 0.f);
            float rs = rsqrtf(var + 1e-5f);
            float c0 = -mu * rs;
            ull rs2 = pk(rs, rs), c02 = pk(c0, c0);

            ull acc2[8];
            #pragma unroll
            for (int h = 0; h < 8; h++) acc2[h] = 0ULL;
            #pragma unroll
            for (int k2 = 0; k2 < 4; k2++) {
                ull x2 = add2(a2[k2], bm2[k2]);
                ull t2 = fma2(x2, rs2, c02);
                ull y2 = relu2(fma2(t2, g2[k2], bt2[k2]));
                const ull* up = &ush[(k2 * 8) * 32 + lane];
                #pragma unroll
                for (int h = 0; h < 8; h++) acc2[h] = fma2(y2, up[h * 32], acc2[h]);
            }
            float acc[8];
            #pragma unroll
            for (int h = 0; h < 8; h++) {
                float lo, hi; upk(acc2[h], lo, hi);
                acc[h] = lo + hi;
            }
            bool b4 = (lane & 16), b3 = (lane & 8), b2 = (lane & 4);
            float v0, v1, v2, v3;
            {
                float t0 = b4 ? acc[0] : acc[4];
                float t1 = b4 ? acc[1] : acc[5];
                float t2_ = b4 ? acc[2] : acc[6];
                float t3 = b4 ? acc[3] : acc[7];
                v0 = (b4 ? acc[4] : acc[0]) + __shfl_xor_sync(0xffffffffu, t0, 16);
                v1 = (b4 ? acc[5] : acc[1]) + __shfl_xor_sync(0xffffffffu, t1, 16);
                v2 = (b4 ? acc[6] : acc[2]) + __shfl_xor_sync(0xffffffffu, t2_, 16);
                v3 = (b4 ? acc[7] : acc[3]) + __shfl_xor_sync(0xffffffffu, t3, 16);
            }
            float w0, w1;
            {
                float t0 = b3 ? v0 : v2;
                float t1 = b3 ? v1 : v3;
                w0 = (b3 ? v2 : v0) + __shfl_xor_sync(0xffffffffu, t0, 8);
                w1 = (b3 ? v3 : v1) + __shfl_xor_sync(0xffffffffu, t1, 8);
            }
            float r;
            {
                float tsel = b2 ? w0 : w1;
                r = (b2 ? w1 : w0) + __shfl_xor_sync(0xffffffffu, tsel, 4);
            }
            r += __shfl_xor_sync(0xffffffffu, r, 2);
            r += __shfl_xor_sync(0xffffffffu, r, 1);
            if ((lane & 3) == 0) e_sh[s][lane >> 2][j] = r;
        }
    }
    __syncthreads();

    // softmax: warp w = head w; loop i slots
    int h = w;
    #pragma unroll 1
    for (int s = 0; s < 4; s++) {
        int i = base + s;
        if (i > 128) break;
        float qv = g_qa[(b * HH + h) * TT + i];
        const float* kap = g_ka + (b * HH + h) * TT;
        const float* bi = g_bias + (((size_t)(b * HH + h) * SS) + (i - 1)) * SS;
        float lg[5];
        float mx = -3.4e38f;
        #pragma unroll
        for (int m = 0; m < 5; m++) {
            int j = lane + 32 * m;
            float L = -3.4e38f;
            if (j <= 128) {
                bool ok = (j >= 1) && (i == 0 || j != i);
                if (!ok) L = -1e9f;
                else {
                    L = e_sh[s][h][j] + qv + kap[j];
                    if (i >= 1) L += bi[j - 1];
                }
            }
            lg[m] = L;
            mx = fmaxf(mx, L);
        }
        #pragma unroll
        for (int off = 16; off; off >>= 1)
            mx = fmaxf(mx, __shfl_xor_sync(0xffffffffu, mx, off));
        float sum = 0.f;
        #pragma unroll
        for (int m = 0; m < 5; m++) {
            int j = lane + 32 * m;
            if (j <= 128) { lg[m] = __expf(lg[m] - mx); sum += lg[m]; }
            else lg[m] = 0.f;
        }
        #pragma unroll
        for (int off = 16; off; off >>= 1)
            sum += __shfl_xor_sync(0xffffffffu, sum, off);
        float inv = 1.f / sum;
        float* ao = out_attn + ((size_t)(b * HH + h) * TT + i) * TT;
        #pragma unroll
        for (int m = 0; m < 5; m++) {
            int j = lane + 32 * m;
            if (j <= 128) ao[j] = lg[m] * inv;
        }
    }
}

// ---------------------------------------------------------------------------
// ctx: block per (b,h,iq). Shared-staged attn rows (scalar coalesced loads).
__global__ void __launch_bounds__(256) k_ctx(const float* __restrict__ attn,
                                             float* __restrict__ out_basis) {
    int t = blockIdx.x;
    int b = t >> 5, h = (t >> 2) & 7, iq = t & 3;
    int i0q = iq * 32;
    int iend = (iq == 3) ? 129 : (i0q + 32);
    int tid = threadIdx.x, w = tid >> 5, lane = tid & 31;

    __shared__ __align__(16) float vsh[TT * 33];
    __shared__ __align__(16) float a_sh[8 * 132];

    for (int idx = tid; idx < TT * 32; idx += 256) {
        int j = idx >> 5, d = idx & 31;
        vsh[j * 33 + d] = g_V[((size_t)b * TT + j) * DD + h * HDIM + d];
    }
    __syncthreads();

    for (int i0 = i0q; i0 < iend; i0 += 8) {
        int rows = iend - i0; if (rows > 8) rows = 8;
        if (w < rows) {
            int i = i0 + w;
            const float* ar = attn + ((size_t)(b * HH + h) * TT + i) * TT;
            #pragma unroll
            for (int m = 0; m < 4; m++)
                a_sh[w * 132 + lane + 32 * m] = ar[lane + 32 * m];
            if (lane == 0) a_sh[w * 132 + 128] = ar[128];
        }
        __syncthreads();
        if (w < rows) {
            int i = i0 + w;
            const float4* arow = (const float4*)(a_sh + w * 132);
            float acc = 0.f;
            #pragma unroll 8
            for (int jj = 0; jj < 32; jj++) {
                float4 av = arow[jj];
                int jb = jj * 4;
                acc = fmaf(av.x, vsh[(jb + 0) * 33 + lane], acc);
                acc = fmaf(av.y, vsh[(jb + 1) * 33 + lane], acc);
                acc = fmaf(av.z, vsh[(jb + 2) * 33 + lane], acc);
                acc = fmaf(av.w, vsh[(jb + 3) * 33 + lane], acc);
            }
            acc = fmaf(a_sh[w * 132 + 128], vsh[128 * 33 + lane], acc);
            out_basis[(((size_t)b * TT + i) * HH + h) * HDIM + lane] = acc;
        }
        __syncthreads();
    }
}

// ---------------------------------------------------------------------------
extern "C" void kernel_launch(void* const* d_in, const int* in_sizes, int n_in,
                              void* d_out, int out_size) {
    const float* desc  = (const float*)d_in[0];
    const float* nv    = (const float*)d_in[1];
    const float* prior = (const float*)d_in[2];
    const float* Wq    = (const float*)d_in[3];
    const float* bq    = (const float*)d_in[4];
    const float* Wk    = (const float*)d_in[5];
    const float* bk    = (const float*)d_in[6];
    const float* Wv    = (const float*)d_in[7];
    const float* bv    = (const float*)d_in[8];
    const float* wa    = (const float*)d_in[9];
    const float* ba    = (const float*)d_in[10];
    const float* We1   = (const float*)d_in[11];
    const float* be1   = (const float*)d_in[12];
    const float* lng   = (const float*)d_in[13];
    const float* lnb   = (const float*)d_in[14];
    const float* We2   = (const float*)d_in[15];
    const float* be2   = (const float*)d_in[16];

    float* out      = (float*)d_out;
    float* out_attn = out + (size_t)BB * TT * HH * HDIM;

    k_setup<<<25, 256>>>(Wq, Wk, We2, wa, bq, bk, be2);
    k_fused<<<453, 256>>>(desc, nv, prior, We1, be1, Wv, bv, ba);
    k_stats<<<64, 256>>>();
    k_edge<<<BB * 33, 256>>>(lng, lnb, out_attn);
    k_ctx<<<BB * HH * 4, 256>>>(out_attn, out);
}